// round 7
// baseline (speedup 1.0000x reference)
#include <cuda_runtime.h>

#define NNODE 32
#define NB    64
#define NDIM  32
#define NSTEP 8
#define NT    16
#define NE    992
#define NP    31
#define NH    64
#define NC    96
#define MEDGE (NE*NB)   // 63488

// ---------------- persistent scratch (device globals; no allocation) ----------
__device__ float g_x[NNODE*NDIM*NB];       // [n][d][b]
__device__ float g_hedge[NE*NH*NB];        // [e][o][b]  (h_edge / post-GRU msgs)
__device__ float g_msgs[NE*NH*NB];         // [e][o][b]  (pre-GRU msgs)
__device__ float g_hnode[NNODE*NB*NC];     // [n][b][c]
__device__ float g_agg[NNODE*NB*NH];       // [n][b][o]

// ---- accurate activations (immune to fast-math demotion) --------------------
__device__ __forceinline__ float exp_acc(float x){
    float u = x * 1.4426950408889634f;          // x * log2(e)
    u = fminf(fmaxf(u, -126.0f), 126.0f);
    float k = rintf(u);
    float f = u - k;                             // |f| <= 0.5, exact
    float t = f * 0.6931471805599453f;           // |t| <= 0.3466
    float p = 1.9841270e-4f;                     // 1/5040
    p = fmaf(p, t, 1.3888889e-3f);               // 1/720
    p = fmaf(p, t, 8.3333333e-3f);               // 1/120
    p = fmaf(p, t, 4.1666667e-2f);               // 1/24
    p = fmaf(p, t, 1.6666667e-1f);               // 1/6
    p = fmaf(p, t, 0.5f);
    p = fmaf(p, t, 1.0f);
    p = fmaf(p, t, 1.0f);                        // e^t
    float s = __int_as_float(((int)k + 127) << 23);
    return p * s;
}
__device__ __forceinline__ float sigm_(float x){
    return __fdiv_rn(1.0f, 1.0f + exp_acc(-x));
}
__device__ __forceinline__ float tanh_(float x){
    float a = fabsf(x);
    float r;
    if (a < 0.17328f){
        // q = e^{-2a} - 1 computed cancellation-free
        float t = -2.0f * a;
        float p = 1.9841270e-4f;
        p = fmaf(p, t, 1.3888889e-3f);
        p = fmaf(p, t, 8.3333333e-3f);
        p = fmaf(p, t, 4.1666667e-2f);
        p = fmaf(p, t, 1.6666667e-1f);
        p = fmaf(p, t, 0.5f);
        p = fmaf(p, t, 1.0f);
        float q = p * t;                         // e^t - 1
        r = __fdiv_rn(-q, 2.0f + q);
    } else {
        float t = exp_acc(-2.0f * a);
        r = __fdiv_rn(1.0f - t, 1.0f + t);
    }
    return copysignf(r, x);
}

// ---------------- prep: g_x[n][d][b] = x[b][n][d][t]  (t < 8) ----------------
__global__ void prep_kernel(const float* __restrict__ x, int t){
    int idx = blockIdx.x*blockDim.x + threadIdx.x;      // (n*32+d)*64+b
    int b = idx & 63, d = (idx>>6)&31, n = idx>>11;
    g_x[idx] = x[(((b*NNODE)+n)*NDIM + d)*NSTEP + t];
}

// ---------------- edge MLP mixture: msgs_pre[e][o][b] -------------------------
// shared: sW1[3*64*64] sW2[3*64*64] sb1[192] sb2[192] sh1[256*65]
__global__ __launch_bounds__(256,1) void edge_mlp_kernel(
    const int* __restrict__ es, const float* __restrict__ z,
    const float* __restrict__ W1, const float* __restrict__ b1,
    const float* __restrict__ W2, const float* __restrict__ b2, int t)
{
    extern __shared__ float sm1[];
    float* sW1 = sm1;
    float* sW2 = sm1 + 12288;
    float* sb1 = sm1 + 24576;
    float* sb2 = sm1 + 24768;
    float* sh1 = sm1 + 24960 + threadIdx.x*65;    // per-thread h1, conflict-free
    {
        float4* d1=(float4*)sW1; const float4* s1=(const float4*)W1;
        for (int i=threadIdx.x;i<3072;i+=256) d1[i]=s1[i];
        float4* d2=(float4*)sW2; const float4* s2=(const float4*)W2;
        for (int i=threadIdx.x;i<3072;i+=256) d2[i]=s2[i];
        if (threadIdx.x<192){ sb1[threadIdx.x]=b1[threadIdx.x]; sb2[threadIdx.x]=b2[threadIdx.x]; }
    }
    __syncthreads();

    int m = blockIdx.x*256 + threadIdx.x;
    int e = m >> 6, b = m & 63;
    int c0 = es[e];        // col = es[0]
    int r0 = es[NE + e];   // row = es[1]
    const float* xr = &g_x[r0*NDIM*NB + b];
    const float* xc = &g_x[c0*NDIM*NB + b];
    const float* zp = &z[(b*NE + e)*3];

    float msum[64];
    #pragma unroll
    for (int o=0;o<64;o++) msum[o]=0.0f;

    #pragma unroll 1
    for (int k=0;k<3;k++){
        // ---- layer 1: in(64) -> h1(64), relu ----
        float acc[64];
        #pragma unroll
        for (int h=0;h<64;h++) acc[h] = sb1[k*64+h];
        const float* w1k = sW1 + k*4096;
        #pragma unroll 1
        for (int i=0;i<32;i++){
            float a = xr[i*NB];
            const float4* w = (const float4*)(w1k + i*64);
            #pragma unroll
            for (int q=0;q<16;q++){ float4 v=w[q];
                acc[4*q+0]+=a*v.x; acc[4*q+1]+=a*v.y; acc[4*q+2]+=a*v.z; acc[4*q+3]+=a*v.w; }
        }
        #pragma unroll 1
        for (int i=0;i<32;i++){
            float a = xc[i*NB];
            const float4* w = (const float4*)(w1k + (32+i)*64);
            #pragma unroll
            for (int q=0;q<16;q++){ float4 v=w[q];
                acc[4*q+0]+=a*v.x; acc[4*q+1]+=a*v.y; acc[4*q+2]+=a*v.z; acc[4*q+3]+=a*v.w; }
        }
        #pragma unroll
        for (int h=0;h<64;h++) sh1[h] = fmaxf(acc[h], 0.0f);

        // ---- layer 2 + relu + z-weighted combine ----
        float zk = zp[k] * (1.0f/3.0f);
        const float* w2k = sW2 + k*4096;
        #pragma unroll
        for (int oc=0; oc<2; oc++){
            float a2[32];
            #pragma unroll
            for (int u=0;u<32;u++) a2[u] = sb2[k*64 + oc*32 + u];
            #pragma unroll 1
            for (int h=0;h<64;h++){
                float a = sh1[h];
                const float4* w = (const float4*)(w2k + h*64 + oc*32);
                #pragma unroll
                for (int q=0;q<8;q++){ float4 v=w[q];
                    a2[4*q+0]+=a*v.x; a2[4*q+1]+=a*v.y; a2[4*q+2]+=a*v.z; a2[4*q+3]+=a*v.w; }
            }
            #pragma unroll
            for (int u=0;u<32;u++) msum[oc*32+u] += zk * fmaxf(a2[u], 0.0f);
        }
    }

    float* op = ((t==0) ? g_hedge : g_msgs) + e*NH*NB + b;
    #pragma unroll
    for (int o=0;o<64;o++) op[o*NB] = msum[o];
}

// ---------------- edge GRU: g_hedge = GRU(g_msgs, g_hedge) --------------------
// shared: sWi[3*64*64] sWh[3*64*64] sbi[192] sbh[192]
__global__ __launch_bounds__(256,1) void edge_gru_kernel(
    const float* __restrict__ Wi, const float* __restrict__ bi,
    const float* __restrict__ Wh, const float* __restrict__ bh)
{
    extern __shared__ float sm2[];
    float* sWi = sm2;
    float* sWh = sm2 + 12288;
    float* sbi = sm2 + 24576;
    float* sbh = sm2 + 24768;
    {
        float4* d1=(float4*)sWi; const float4* s1=(const float4*)Wi;
        for (int i=threadIdx.x;i<3072;i+=256) d1[i]=s1[i];
        float4* d2=(float4*)sWh; const float4* s2=(const float4*)Wh;
        for (int i=threadIdx.x;i<3072;i+=256) d2[i]=s2[i];
        if (threadIdx.x<192){ sbi[threadIdx.x]=bi[threadIdx.x]; sbh[threadIdx.x]=bh[threadIdx.x]; }
    }
    __syncthreads();

    int m = blockIdx.x*256 + threadIdx.x;
    int e = m>>6, b = m&63;
    const float* inp = g_msgs  + e*NH*NB + b;
    float*       hed = g_hedge + e*NH*NB + b;

    float res[64];
    #pragma unroll
    for (int oc=0; oc<2; oc++){
        float aR[32], aI[32], aNi[32], aNh[32];
        #pragma unroll
        for (int u=0;u<32;u++){
            int h = oc*32+u;
            aR[u]  = sbi[h]     + sbh[h];
            aI[u]  = sbi[64+h]  + sbh[64+h];
            aNi[u] = sbi[128+h];
            aNh[u] = sbh[128+h];
        }
        #pragma unroll 1
        for (int j=0;j<64;j++){
            float a  = inp[j*NB];
            float hh = hed[j*NB];
            const float4* wi0 = (const float4*)(sWi +        j*64 + oc*32);
            const float4* wi1 = (const float4*)(sWi + 4096 + j*64 + oc*32);
            const float4* wi2 = (const float4*)(sWi + 8192 + j*64 + oc*32);
            const float4* wh0 = (const float4*)(sWh +        j*64 + oc*32);
            const float4* wh1 = (const float4*)(sWh + 4096 + j*64 + oc*32);
            const float4* wh2 = (const float4*)(sWh + 8192 + j*64 + oc*32);
            #pragma unroll
            for (int q=0;q<8;q++){
                float4 v;
                v=wi0[q]; aR[4*q]+=a *v.x; aR[4*q+1]+=a *v.y; aR[4*q+2]+=a *v.z; aR[4*q+3]+=a *v.w;
                v=wh0[q]; aR[4*q]+=hh*v.x; aR[4*q+1]+=hh*v.y; aR[4*q+2]+=hh*v.z; aR[4*q+3]+=hh*v.w;
                v=wi1[q]; aI[4*q]+=a *v.x; aI[4*q+1]+=a *v.y; aI[4*q+2]+=a *v.z; aI[4*q+3]+=a *v.w;
                v=wh1[q]; aI[4*q]+=hh*v.x; aI[4*q+1]+=hh*v.y; aI[4*q+2]+=hh*v.z; aI[4*q+3]+=hh*v.w;
                v=wi2[q]; aNi[4*q]+=a *v.x; aNi[4*q+1]+=a *v.y; aNi[4*q+2]+=a *v.z; aNi[4*q+3]+=a *v.w;
                v=wh2[q]; aNh[4*q]+=hh*v.x; aNh[4*q+1]+=hh*v.y; aNh[4*q+2]+=hh*v.z; aNh[4*q+3]+=hh*v.w;
            }
        }
        #pragma unroll
        for (int u=0;u<32;u++){
            int h = oc*32+u;
            float r  = sigm_(aR[u]);
            float ii = sigm_(aI[u]);
            float nn = tanh_(aNi[u] + r*aNh[u]);
            res[h] = (1.0f-ii)*nn + ii*hed[h*NB];
        }
    }
    #pragma unroll
    for (int h=0;h<64;h++) hed[h*NB] = res[h];   // only after ALL reads done
}

// ---------------- scatter-mean: g_agg[n][b][o] = mean_e msgs[e][o][b] ---------
__global__ void agg_kernel(){
    int idx = blockIdx.x*blockDim.x + threadIdx.x;   // ((n*64+o)*64+b)
    int b = idx & 63, o = (idx>>6)&63, n = idx>>12;
    const float* p = g_hedge + ((n*NP)*NH + o)*NB + b;
    float s = 0.0f;
    #pragma unroll
    for (int e2=0;e2<NP;e2++) s += p[e2*NH*NB];
    g_agg[(n*NB+b)*NH + o] = s * (1.0f/31.0f);
}

// ---------------- node: cat -> GRU96 -> MLP -> x update + outputs -------------
__global__ __launch_bounds__(256) void node_kernel(
    const float* __restrict__ gnWi, const float* __restrict__ gnbi,
    const float* __restrict__ gnWh, const float* __restrict__ gnbh,
    const float* __restrict__ oW1, const float* __restrict__ ob1,
    const float* __restrict__ oW2, const float* __restrict__ ob2,
    const float* __restrict__ oW3, const float* __restrict__ ob3,
    float* __restrict__ out, int t)
{
    __shared__ float scat[8][NC];
    __shared__ float shid[8][NC];
    __shared__ float stmp[8][64];
    int w = threadIdx.x>>5, lane = threadIdx.x&31;
    int m = blockIdx.x*8 + w;
    int n = m>>6, b = m&63;

    // build cat = [x_in(32), agg(64)]
    #pragma unroll
    for (int c=lane;c<NC;c+=32){
        float v;
        if (c<NDIM) v = g_x[(n*NDIM+c)*NB + b];
        else        v = g_agg[(n*NB+b)*NH + (c-NDIM)];
        scat[w][c] = v;
    }
    if (t>0){
        #pragma unroll
        for (int c=lane;c<NC;c+=32) shid[w][c] = g_hnode[(n*NB+b)*NC + c];
    }
    __syncwarp();

    if (t>0){
        float aR[3],aI[3],aNi[3],aNh[3];
        #pragma unroll
        for (int u=0;u<3;u++){
            int h=lane+u*32;
            aR[u]=gnbi[h]+gnbh[h];
            aI[u]=gnbi[96+h]+gnbh[96+h];
            aNi[u]=gnbi[192+h];
            aNh[u]=gnbh[192+h];
        }
        #pragma unroll 1
        for (int j=0;j<NC;j++){
            float a  = scat[w][j];
            float hh = shid[w][j];
            #pragma unroll
            for (int u=0;u<3;u++){
                int h = lane+u*32;
                aR[u]  += a*gnWi[j*96+h]        + hh*gnWh[j*96+h];
                aI[u]  += a*gnWi[9216+j*96+h]   + hh*gnWh[9216+j*96+h];
                aNi[u] += a*gnWi[18432+j*96+h];
                aNh[u] += hh*gnWh[18432+j*96+h];
            }
        }
        float nc[3];
        #pragma unroll
        for (int u=0;u<3;u++){
            int h = lane+u*32;
            float r=sigm_(aR[u]), ii=sigm_(aI[u]);
            float nn=tanh_(aNi[u] + r*aNh[u]);
            nc[u] = (1.0f-ii)*nn + ii*shid[w][h];
        }
        __syncwarp();
        #pragma unroll
        for (int u=0;u<3;u++) scat[w][lane+u*32] = nc[u];
    }
    __syncwarp();

    // h_node <- cat (post-GRU when t>0)
    #pragma unroll
    for (int c=lane;c<NC;c+=32) g_hnode[(n*NB+b)*NC + c] = scat[w][c];

    // out MLP: 96 -> 64 -> 64 -> 32
    float a0 = ob1[lane], a1 = ob1[lane+32];
    #pragma unroll 1
    for (int j=0;j<NC;j++){
        float v = scat[w][j];
        a0 += v*oW1[j*64+lane];
        a1 += v*oW1[j*64+lane+32];
    }
    stmp[w][lane]    = fmaxf(a0,0.0f);
    stmp[w][lane+32] = fmaxf(a1,0.0f);
    __syncwarp();

    float c0v = ob2[lane], c1v = ob2[lane+32];
    #pragma unroll 1
    for (int j=0;j<64;j++){
        float v = stmp[w][j];
        c0v += v*oW2[j*64+lane];
        c1v += v*oW2[j*64+lane+32];
    }
    __syncwarp();
    stmp[w][lane]    = fmaxf(c0v,0.0f);
    stmp[w][lane+32] = fmaxf(c1v,0.0f);
    __syncwarp();

    float a = ob3[lane];
    #pragma unroll 1
    for (int j=0;j<64;j++) a += stmp[w][j]*oW3[j*32+lane];

    int xi = (n*NDIM+lane)*NB + b;
    float xn = g_x[xi] + a;
    g_x[xi] = xn;

    // outputs: (x_hat[...,-8:], x_hat, x_hat) concatenated
    int base = (b*NNODE+n)*NDIM + lane;
    out[524288  + base*NT + t] = xn;
    out[1572864 + base*NT + t] = xn;
    if (t>=NSTEP) out[base*NSTEP + (t-NSTEP)] = xn;
}

extern "C" void kernel_launch(void* const* d_in, const int* in_sizes, int n_in,
                              void* d_out, int out_size) {
    const float* x     = (const float*)d_in[0];
    const float* z     = (const float*)d_in[1];
    const int*   es    = (const int*)d_in[2];
    // d_in[3..5]: masks (all-zero; unused by the math)
    const float* msgW1 = (const float*)d_in[6];
    const float* msgb1 = (const float*)d_in[7];
    const float* msgW2 = (const float*)d_in[8];
    const float* msgb2 = (const float*)d_in[9];
    const float* oW1   = (const float*)d_in[10];
    const float* ob1   = (const float*)d_in[11];
    const float* oW2   = (const float*)d_in[12];
    const float* ob2   = (const float*)d_in[13];
    const float* oW3   = (const float*)d_in[14];
    const float* ob3   = (const float*)d_in[15];
    const float* geWi  = (const float*)d_in[16];
    const float* gebi  = (const float*)d_in[17];
    const float* geWh  = (const float*)d_in[18];
    const float* gebh  = (const float*)d_in[19];
    const float* gnWi  = (const float*)d_in[20];
    const float* gnbi  = (const float*)d_in[21];
    const float* gnWh  = (const float*)d_in[22];
    const float* gnbh  = (const float*)d_in[23];
    float* out = (float*)d_out;

    const int SM_MLP = (24960 + 256*65)*4;   // 166,400 B
    const int SM_GRU = 24960*4;              //  99,840 B
    cudaFuncSetAttribute(edge_mlp_kernel, cudaFuncAttributeMaxDynamicSharedMemorySize, SM_MLP);
    cudaFuncSetAttribute(edge_gru_kernel, cudaFuncAttributeMaxDynamicSharedMemorySize, SM_GRU);

    for (int t=0;t<NT;t++){
        if (t<NSTEP) prep_kernel<<<256,256>>>(x,t);
        edge_mlp_kernel<<<MEDGE/256,256,SM_MLP>>>(es,z,msgW1,msgb1,msgW2,msgb2,t);
        if (t>0) edge_gru_kernel<<<MEDGE/256,256,SM_GRU>>>(geWi,gebi,geWh,gebh);
        agg_kernel<<<512,256>>>();
        node_kernel<<<256,256>>>(gnWi,gnbi,gnWh,gnbh,oW1,ob1,oW2,ob2,oW3,ob3,out,t);
    }
}

// round 9
// speedup vs baseline: 1.0957x; 1.0957x over previous
#include <cuda_runtime.h>

#define NNODE 32
#define NB    64
#define NDIM  32
#define NSTEP 8
#define NT    16
#define NE    992
#define NP    31
#define NH    64
#define NC    96
#define MEDGE (NE*NB)   // 63488

typedef unsigned long long u64;

// ---------------- persistent scratch (device globals; no allocation) ----------
__device__ float g_x[NNODE*NDIM*NB];       // [n][d][b]
__device__ float g_hedge[NE*NH*NB];        // [e][o][b]  (h_edge / post-GRU msgs)
__device__ float g_msgs[NE*NH*NB];         // [e][o][b]  (pre-GRU msgs)
__device__ float g_hnode[NNODE*NB*NC];     // [n][b][c]
__device__ float g_agg[NNODE*NB*NH];       // [n][b][o]

// ---- accurate activations (immune to fast-math demotion) --------------------
__device__ __forceinline__ float exp_acc(float x){
    float u = x * 1.4426950408889634f;          // x * log2(e)
    u = fminf(fmaxf(u, -126.0f), 126.0f);
    float k = rintf(u);
    float f = u - k;                             // |f| <= 0.5, exact
    float t = f * 0.6931471805599453f;           // |t| <= 0.3466
    float p = 1.9841270e-4f;                     // 1/5040
    p = fmaf(p, t, 1.3888889e-3f);               // 1/720
    p = fmaf(p, t, 8.3333333e-3f);               // 1/120
    p = fmaf(p, t, 4.1666667e-2f);               // 1/24
    p = fmaf(p, t, 1.6666667e-1f);               // 1/6
    p = fmaf(p, t, 0.5f);
    p = fmaf(p, t, 1.0f);
    p = fmaf(p, t, 1.0f);                        // e^t
    float s = __int_as_float(((int)k + 127) << 23);
    return p * s;
}
__device__ __forceinline__ float sigm_(float x){
    return __fdiv_rn(1.0f, 1.0f + exp_acc(-x));
}
__device__ __forceinline__ float tanh_(float x){
    float a = fabsf(x);
    float r;
    if (a < 0.17328f){
        float t = -2.0f * a;
        float p = 1.9841270e-4f;
        p = fmaf(p, t, 1.3888889e-3f);
        p = fmaf(p, t, 8.3333333e-3f);
        p = fmaf(p, t, 4.1666667e-2f);
        p = fmaf(p, t, 1.6666667e-1f);
        p = fmaf(p, t, 0.5f);
        p = fmaf(p, t, 1.0f);
        float q = p * t;                         // e^t - 1, cancellation-free
        r = __fdiv_rn(-q, 2.0f + q);
    } else {
        float t = exp_acc(-2.0f * a);
        r = __fdiv_rn(1.0f - t, 1.0f + t);
    }
    return copysignf(r, x);
}

// ---- packed f32x2 helpers (sm_103a dual-lane fp32 FMA; bit-identical IEEE) --
__device__ __forceinline__ u64 pack2s(float x){           // (x, x)
    u64 r; asm("mov.b64 %0, {%1, %1};" : "=l"(r) : "f"(x)); return r;
}
__device__ __forceinline__ void unpack2(u64 v, float &x, float &y){
    asm("mov.b64 {%0, %1}, %2;" : "=f"(x), "=f"(y) : "l"(v));
}
__device__ __forceinline__ void ffma2(u64 &d, u64 a, u64 b){
    asm("fma.rn.f32x2 %0, %1, %2, %0;" : "+l"(d) : "l"(a), "l"(b));
}

// ---------------- prep: g_x[n][d][b] = x[b][n][d][t]  (t < 8) ----------------
__global__ void prep_kernel(const float* __restrict__ x, int t){
    int idx = blockIdx.x*blockDim.x + threadIdx.x;      // (n*32+d)*64+b
    int b = idx & 63, d = (idx>>6)&31, n = idx>>11;
    g_x[idx] = x[(((b*NNODE)+n)*NDIM + d)*NSTEP + t];
}

// ---------------- edge MLP mixture: msgs_pre[e][o][b] -------------------------
// shared: sW1[3*64*64] sW2[3*64*64] sb1[192] sb2[192] sh1[256*65]
__global__ __launch_bounds__(256,1) void edge_mlp_kernel(
    const int* __restrict__ es, const float* __restrict__ z,
    const float* __restrict__ W1, const float* __restrict__ b1,
    const float* __restrict__ W2, const float* __restrict__ b2, int t)
{
    extern __shared__ float sm1[];
    float* sW1 = sm1;
    float* sW2 = sm1 + 12288;
    float* sb1 = sm1 + 24576;
    float* sb2 = sm1 + 24768;
    float* sh1 = sm1 + 24960 + threadIdx.x*65;    // per-thread h1, conflict-free
    {
        float4* d1=(float4*)sW1; const float4* s1=(const float4*)W1;
        for (int i=threadIdx.x;i<3072;i+=256) d1[i]=s1[i];
        float4* d2=(float4*)sW2; const float4* s2=(const float4*)W2;
        for (int i=threadIdx.x;i<3072;i+=256) d2[i]=s2[i];
        if (threadIdx.x<192){ sb1[threadIdx.x]=b1[threadIdx.x]; sb2[threadIdx.x]=b2[threadIdx.x]; }
    }
    __syncthreads();

    int m = blockIdx.x*256 + threadIdx.x;
    int e = m >> 6, b = m & 63;
    int c0 = es[e];        // col = es[0]
    int r0 = es[NE + e];   // row = es[1]
    const float* xr = &g_x[r0*NDIM*NB + b];
    const float* xc = &g_x[c0*NDIM*NB + b];
    const float* zp = &z[(b*NE + e)*3];

    float msum[64];
    #pragma unroll
    for (int o=0;o<64;o++) msum[o]=0.0f;

    #pragma unroll 1
    for (int k=0;k<3;k++){
        // ---- layer 1: in(64) -> h1(64), relu; packed pairs (2p, 2p+1) ----
        u64 acc2[32];
        {
            const u64* bb = (const u64*)(sb1 + k*64);
            #pragma unroll
            for (int p=0;p<32;p++) acc2[p] = bb[p];
        }
        const float* w1k = sW1 + k*4096;
        #pragma unroll 1
        for (int i=0;i<32;i++){
            u64 av = pack2s(xr[i*NB]);
            const ulonglong2* w = (const ulonglong2*)(w1k + i*64);
            #pragma unroll
            for (int q=0;q<16;q++){ ulonglong2 v=w[q];
                ffma2(acc2[2*q], av, v.x); ffma2(acc2[2*q+1], av, v.y); }
        }
        #pragma unroll 1
        for (int i=0;i<32;i++){
            u64 av = pack2s(xc[i*NB]);
            const ulonglong2* w = (const ulonglong2*)(w1k + (32+i)*64);
            #pragma unroll
            for (int q=0;q<16;q++){ ulonglong2 v=w[q];
                ffma2(acc2[2*q], av, v.x); ffma2(acc2[2*q+1], av, v.y); }
        }
        #pragma unroll
        for (int p=0;p<32;p++){
            float lo, hi; unpack2(acc2[p], lo, hi);
            sh1[2*p]   = fmaxf(lo, 0.0f);
            sh1[2*p+1] = fmaxf(hi, 0.0f);
        }

        // ---- layer 2 + relu + z-weighted combine ----
        float zk = zp[k] * (1.0f/3.0f);
        const float* w2k = sW2 + k*4096;
        #pragma unroll
        for (int oc=0; oc<2; oc++){
            u64 a2[16];
            {
                const u64* bb = (const u64*)(sb2 + k*64 + oc*32);
                #pragma unroll
                for (int p=0;p<16;p++) a2[p] = bb[p];
            }
            #pragma unroll 1
            for (int h=0;h<64;h++){
                u64 av = pack2s(sh1[h]);
                const ulonglong2* w = (const ulonglong2*)(w2k + h*64 + oc*32);
                #pragma unroll
                for (int q=0;q<8;q++){ ulonglong2 v=w[q];
                    ffma2(a2[2*q], av, v.x); ffma2(a2[2*q+1], av, v.y); }
            }
            #pragma unroll
            for (int p=0;p<16;p++){
                float lo, hi; unpack2(a2[p], lo, hi);
                msum[oc*32+2*p]   += zk * fmaxf(lo, 0.0f);
                msum[oc*32+2*p+1] += zk * fmaxf(hi, 0.0f);
            }
        }
    }

    float* op = ((t==0) ? g_hedge : g_msgs) + e*NH*NB + b;
    #pragma unroll
    for (int o=0;o<64;o++) op[o*NB] = msum[o];
}

// ---------------- edge GRU: g_hedge = GRU(g_msgs, g_hedge) --------------------
// f32x2; NOTE: q loop runs 0..7 (8 ulonglong2 = 32 floats per oc-half).
// Round-3 bug was q<4 here (half the outputs never accumulated).
__global__ __launch_bounds__(256,1) void edge_gru_kernel(
    const float* __restrict__ Wi, const float* __restrict__ bi,
    const float* __restrict__ Wh, const float* __restrict__ bh)
{
    extern __shared__ float sm2[];
    float* sWi = sm2;
    float* sWh = sm2 + 12288;
    float* sbi = sm2 + 24576;
    float* sbh = sm2 + 24768;
    {
        float4* d1=(float4*)sWi; const float4* s1=(const float4*)Wi;
        for (int i=threadIdx.x;i<3072;i+=256) d1[i]=s1[i];
        float4* d2=(float4*)sWh; const float4* s2=(const float4*)Wh;
        for (int i=threadIdx.x;i<3072;i+=256) d2[i]=s2[i];
        if (threadIdx.x<192){ sbi[threadIdx.x]=bi[threadIdx.x]; sbh[threadIdx.x]=bh[threadIdx.x]; }
    }
    __syncthreads();

    int m = blockIdx.x*256 + threadIdx.x;
    int e = m>>6, b = m&63;
    const float* inp = g_msgs  + e*NH*NB + b;
    float*       hed = g_hedge + e*NH*NB + b;

    float res[64];
    #pragma unroll 1
    for (int oc=0; oc<2; oc++){
        u64 aR2[16], aI2[16], aNi2[16], aNh2[16];
        {
            const u64* bi0 = (const u64*)(sbi +       oc*32);
            const u64* bi1 = (const u64*)(sbi + 64  + oc*32);
            const u64* bi2 = (const u64*)(sbi + 128 + oc*32);
            const u64* bh0 = (const u64*)(sbh +       oc*32);
            const u64* bh1 = (const u64*)(sbh + 64  + oc*32);
            const u64* bh2 = (const u64*)(sbh + 128 + oc*32);
            #pragma unroll
            for (int p=0;p<16;p++){
                float x0,y0,x1,y1;
                unpack2(bi0[p],x0,y0); unpack2(bh0[p],x1,y1);
                float lo = x0+x1, hi = y0+y1;
                asm("mov.b64 %0, {%1, %2};" : "=l"(aR2[p]) : "f"(lo), "f"(hi));
                unpack2(bi1[p],x0,y0); unpack2(bh1[p],x1,y1);
                lo = x0+x1; hi = y0+y1;
                asm("mov.b64 %0, {%1, %2};" : "=l"(aI2[p]) : "f"(lo), "f"(hi));
                aNi2[p] = bi2[p];
                aNh2[p] = bh2[p];
            }
        }
        #pragma unroll 1
        for (int j=0;j<64;j++){
            u64 av = pack2s(inp[j*NB]);
            u64 hv = pack2s(hed[j*NB]);
            const ulonglong2* wi0 = (const ulonglong2*)(sWi +        j*64 + oc*32);
            const ulonglong2* wi1 = (const ulonglong2*)(sWi + 4096 + j*64 + oc*32);
            const ulonglong2* wi2 = (const ulonglong2*)(sWi + 8192 + j*64 + oc*32);
            const ulonglong2* wh0 = (const ulonglong2*)(sWh +        j*64 + oc*32);
            const ulonglong2* wh1 = (const ulonglong2*)(sWh + 4096 + j*64 + oc*32);
            const ulonglong2* wh2 = (const ulonglong2*)(sWh + 8192 + j*64 + oc*32);
            #pragma unroll
            for (int q=0;q<8;q++){           // 8 x ulonglong2 = full 32-float half
                ulonglong2 v;
                v=wi0[q]; ffma2(aR2[2*q],  av, v.x); ffma2(aR2[2*q+1],  av, v.y);
                v=wh0[q]; ffma2(aR2[2*q],  hv, v.x); ffma2(aR2[2*q+1],  hv, v.y);
                v=wi1[q]; ffma2(aI2[2*q],  av, v.x); ffma2(aI2[2*q+1],  av, v.y);
                v=wh1[q]; ffma2(aI2[2*q],  hv, v.x); ffma2(aI2[2*q+1],  hv, v.y);
                v=wi2[q]; ffma2(aNi2[2*q], av, v.x); ffma2(aNi2[2*q+1], av, v.y);
                v=wh2[q]; ffma2(aNh2[2*q], hv, v.x); ffma2(aNh2[2*q+1], hv, v.y);
            }
        }
        #pragma unroll
        for (int p=0;p<16;p++){
            float rlo,rhi, ilo,ihi, nilo,nihi, nhlo,nhhi;
            unpack2(aR2[p],  rlo,  rhi);
            unpack2(aI2[p],  ilo,  ihi);
            unpack2(aNi2[p], nilo, nihi);
            unpack2(aNh2[p], nhlo, nhhi);
            {
                int h = oc*32 + 2*p;
                float r  = sigm_(rlo);
                float ii = sigm_(ilo);
                float nn = tanh_(nilo + r*nhlo);
                res[h] = (1.0f-ii)*nn + ii*hed[h*NB];
            }
            {
                int h = oc*32 + 2*p + 1;
                float r  = sigm_(rhi);
                float ii = sigm_(ihi);
                float nn = tanh_(nihi + r*nhhi);
                res[h] = (1.0f-ii)*nn + ii*hed[h*NB];
            }
        }
    }
    #pragma unroll
    for (int h=0;h<64;h++) hed[h*NB] = res[h];   // only after ALL reads done
}

// ---------------- scatter-mean: g_agg[n][b][o] = mean_e msgs[e][o][b] ---------
__global__ void agg_kernel(){
    int idx = blockIdx.x*blockDim.x + threadIdx.x;   // ((n*64+o)*64+b)
    int b = idx & 63, o = (idx>>6)&63, n = idx>>12;
    const float* p = g_hedge + ((n*NP)*NH + o)*NB + b;
    float s = 0.0f;
    #pragma unroll
    for (int e2=0;e2<NP;e2++) s += p[e2*NH*NB];
    g_agg[(n*NB+b)*NH + o] = s * (1.0f/31.0f);
}

// ---------------- node: cat -> GRU96 -> MLP -> x update + outputs -------------
__global__ __launch_bounds__(256) void node_kernel(
    const float* __restrict__ gnWi, const float* __restrict__ gnbi,
    const float* __restrict__ gnWh, const float* __restrict__ gnbh,
    const float* __restrict__ oW1, const float* __restrict__ ob1,
    const float* __restrict__ oW2, const float* __restrict__ ob2,
    const float* __restrict__ oW3, const float* __restrict__ ob3,
    float* __restrict__ out, int t)
{
    __shared__ float scat[8][NC];
    __shared__ float shid[8][NC];
    __shared__ float stmp[8][64];
    int w = threadIdx.x>>5, lane = threadIdx.x&31;
    int m = blockIdx.x*8 + w;
    int n = m>>6, b = m&63;

    // build cat = [x_in(32), agg(64)]
    #pragma unroll
    for (int c=lane;c<NC;c+=32){
        float v;
        if (c<NDIM) v = g_x[(n*NDIM+c)*NB + b];
        else        v = g_agg[(n*NB+b)*NH + (c-NDIM)];
        scat[w][c] = v;
    }
    if (t>0){
        #pragma unroll
        for (int c=lane;c<NC;c+=32) shid[w][c] = g_hnode[(n*NB+b)*NC + c];
    }
    __syncwarp();

    if (t>0){
        float aR[3],aI[3],aNi[3],aNh[3];
        #pragma unroll
        for (int u=0;u<3;u++){
            int h=lane+u*32;
            aR[u]=gnbi[h]+gnbh[h];
            aI[u]=gnbi[96+h]+gnbh[96+h];
            aNi[u]=gnbi[192+h];
            aNh[u]=gnbh[192+h];
        }
        #pragma unroll 4
        for (int j=0;j<NC;j++){
            float a  = scat[w][j];
            float hh = shid[w][j];
            #pragma unroll
            for (int u=0;u<3;u++){
                int h = lane+u*32;
                aR[u]  += a*gnWi[j*96+h]        + hh*gnWh[j*96+h];
                aI[u]  += a*gnWi[9216+j*96+h]   + hh*gnWh[9216+j*96+h];
                aNi[u] += a*gnWi[18432+j*96+h];
                aNh[u] += hh*gnWh[18432+j*96+h];
            }
        }
        float nc[3];
        #pragma unroll
        for (int u=0;u<3;u++){
            int h = lane+u*32;
            float r=sigm_(aR[u]), ii=sigm_(aI[u]);
            float nn=tanh_(aNi[u] + r*aNh[u]);
            nc[u] = (1.0f-ii)*nn + ii*shid[w][h];
        }
        __syncwarp();
        #pragma unroll
        for (int u=0;u<3;u++) scat[w][lane+u*32] = nc[u];
    }
    __syncwarp();

    // h_node <- cat (post-GRU when t>0)
    #pragma unroll
    for (int c=lane;c<NC;c+=32) g_hnode[(n*NB+b)*NC + c] = scat[w][c];

    // out MLP: 96 -> 64 -> 64 -> 32
    float a0 = ob1[lane], a1 = ob1[lane+32];
    #pragma unroll 4
    for (int j=0;j<NC;j++){
        float v = scat[w][j];
        a0 += v*oW1[j*64+lane];
        a1 += v*oW1[j*64+lane+32];
    }
    stmp[w][lane]    = fmaxf(a0,0.0f);
    stmp[w][lane+32] = fmaxf(a1,0.0f);
    __syncwarp();

    float c0v = ob2[lane], c1v = ob2[lane+32];
    #pragma unroll 4
    for (int j=0;j<64;j++){
        float v = stmp[w][j];
        c0v += v*oW2[j*64+lane];
        c1v += v*oW2[j*64+lane+32];
    }
    __syncwarp();
    stmp[w][lane]    = fmaxf(c0v,0.0f);
    stmp[w][lane+32] = fmaxf(c1v,0.0f);
    __syncwarp();

    float a = ob3[lane];
    #pragma unroll 4
    for (int j=0;j<64;j++) a += stmp[w][j]*oW3[j*32+lane];

    int xi = (n*NDIM+lane)*NB + b;
    float xn = g_x[xi] + a;
    g_x[xi] = xn;

    // outputs: (x_hat[...,-8:], x_hat, x_hat) concatenated
    int base = (b*NNODE+n)*NDIM + lane;
    out[524288  + base*NT + t] = xn;
    out[1572864 + base*NT + t] = xn;
    if (t>=NSTEP) out[base*NSTEP + (t-NSTEP)] = xn;
}

extern "C" void kernel_launch(void* const* d_in, const int* in_sizes, int n_in,
                              void* d_out, int out_size) {
    const float* x     = (const float*)d_in[0];
    const float* z     = (const float*)d_in[1];
    const int*   es    = (const int*)d_in[2];
    // d_in[3..5]: masks (all-zero; unused by the math)
    const float* msgW1 = (const float*)d_in[6];
    const float* msgb1 = (const float*)d_in[7];
    const float* msgW2 = (const float*)d_in[8];
    const float* msgb2 = (const float*)d_in[9];
    const float* oW1   = (const float*)d_in[10];
    const float* ob1   = (const float*)d_in[11];
    const float* oW2   = (const float*)d_in[12];
    const float* ob2   = (const float*)d_in[13];
    const float* oW3   = (const float*)d_in[14];
    const float* ob3   = (const float*)d_in[15];
    const float* geWi  = (const float*)d_in[16];
    const float* gebi  = (const float*)d_in[17];
    const float* geWh  = (const float*)d_in[18];
    const float* gebh  = (const float*)d_in[19];
    const float* gnWi  = (const float*)d_in[20];
    const float* gnbi  = (const float*)d_in[21];
    const float* gnWh  = (const float*)d_in[22];
    const float* gnbh  = (const float*)d_in[23];
    float* out = (float*)d_out;

    const int SM_MLP = (24960 + 256*65)*4;   // 166,400 B
    const int SM_GRU = 24960*4;              //  99,840 B
    cudaFuncSetAttribute(edge_mlp_kernel, cudaFuncAttributeMaxDynamicSharedMemorySize, SM_MLP);
    cudaFuncSetAttribute(edge_gru_kernel, cudaFuncAttributeMaxDynamicSharedMemorySize, SM_GRU);

    for (int t=0;t<NT;t++){
        if (t<NSTEP) prep_kernel<<<256,256>>>(x,t);
        edge_mlp_kernel<<<MEDGE/256,256,SM_MLP>>>(es,z,msgW1,msgb1,msgW2,msgb2,t);
        if (t>0) edge_gru_kernel<<<MEDGE/256,256,SM_GRU>>>(geWi,gebi,geWh,gebh);
        agg_kernel<<<512,256>>>();
        node_kernel<<<256,256>>>(gnWi,gnbi,gnWh,gnbh,oW1,ob1,oW2,ob2,oW3,ob3,out,t);
    }
}